// round 16
// baseline (speedup 1.0000x reference)
#include <cuda_runtime.h>
#include <cuda_fp16.h>
#include <cstdint>

#define Bdim 4
#define Tdim 4
#define Cdim 32
#define Ndim 16384
#define Fdim 64
#define Kdim 9
#define TILE_N 128
#define THREADS 128

// pitch: 32 fp16 = 64B data + 16B pad = 80B (20-word stride, conflict-free ldmatrix)
#define PROW 80
// smem layout (A not staged; xT region reused as epilogue stage)
#define OFF_XT 0                        // 136 n-rows x 80B = 10880
#define OFF_WS 10880                    // float [9][128]   =  4608
#define SMEM_TOTAL 15488
#define SPITCH 132                      // epilogue stage pitch (floats)

// A weights in FRAGMENT ORDER: [t][k][fh][m][s] -> 128 uint32 (lane*4 + reg i)
// element: f = fh*32 + m*16 + (i&1)*8 + (l>>2), c = s*16 + (i>>1)*8 + 2*(l&3) (+1)
__device__ __align__(16) unsigned g_wAf[Tdim * Kdim * 2 * 2 * 2 * 128];   // 147456 B

__global__ void prep_w(const float* __restrict__ w) {
    int idx = blockIdx.x * 256 + threadIdx.x;
    if (idx >= Tdim * Kdim * 2 * 2 * 2 * 128) return;   // 36864
    int i  = idx & 3;
    int l  = (idx >> 2) & 31;
    int s  = (idx >> 7) & 1;
    int m  = (idx >> 8) & 1;
    int fh = (idx >> 9) & 1;
    int r  = idx >> 10;                  // t*9 + k
    int k  = r % 9, t = r / 9;
    int f  = fh * 32 + m * 16 + (i & 1) * 8 + (l >> 2);
    int c  = s * 16 + (i >> 1) * 8 + 2 * (l & 3);
    float v0 = w[((t * Fdim + f) * Cdim + c) * Kdim + k];
    float v1 = w[((t * Fdim + f) * Cdim + c + 1) * Kdim + k];
    __half2 h2v = __floats2half2_rn(v0, v1);
    g_wAf[idx] = *(unsigned*)&h2v;
}

__device__ __forceinline__ uint32_t smem_u32(const void* p) {
    uint32_t a;
    asm("{ .reg .u64 t; cvta.to.shared.u64 t, %1; cvt.u32.u64 %0, t; }" : "=r"(a) : "l"(p));
    return a;
}

#define LDSM_X4(r0,r1,r2,r3, addr) \
    asm volatile("ldmatrix.sync.aligned.m8n8.x4.shared.b16 {%0,%1,%2,%3}, [%4];" \
        : "=r"(r0),"=r"(r1),"=r"(r2),"=r"(r3) : "r"(addr))

// accumulate form: d = a*b + d
#define MMAF16(c, a, b0,b1) \
    asm volatile("mma.sync.aligned.m16n8k16.row.col.f32.f16.f16.f32 " \
        "{%0,%1,%2,%3},{%4,%5,%6,%7},{%8,%9},{%0,%1,%2,%3};" \
        : "+f"((c)[0]),"+f"((c)[1]),"+f"((c)[2]),"+f"((c)[3]) \
        : "r"((a)[0]),"r"((a)[1]),"r"((a)[2]),"r"((a)[3]),"r"(b0),"r"(b1))

// init form: d = a*b + 0   (no pre-zeroing of d needed; exact same arithmetic)
#define MMAF16_Z(d, a, b0,b1) \
    asm volatile("mma.sync.aligned.m16n8k16.row.col.f32.f16.f16.f32 " \
        "{%0,%1,%2,%3},{%4,%5,%6,%7},{%8,%9},{%10,%10,%10,%10};" \
        : "=f"((d)[0]),"=f"((d)[1]),"=f"((d)[2]),"=f"((d)[3]) \
        : "r"((a)[0]),"r"((a)[1]),"r"((a)[2]),"r"((a)[3]),"r"(b0),"r"(b1),"f"(0.0f))

__global__ __launch_bounds__(THREADS, 4)
void sepconv_mma_kernel(const float* __restrict__ x,
                        const float* __restrict__ coords,
                        const unsigned* __restrict__ sigma_p,
                        float* __restrict__ out)
{
    extern __shared__ __align__(16) unsigned char sm[];
    float* ws = (float*)(sm + OFF_WS);     // [9][128]

    const int tid  = threadIdx.x;
    const int warp = tid >> 5;             // 0..3
    const int lane = tid & 31;
    const int bt   = blockIdx.y;
    const int t    = bt & (Tdim - 1);
    const int n0   = blockIdx.x * TILE_N;
    const uint32_t smb = smem_u32(sm);

    unsigned sb = *sigma_p;
    float sigma = (sb < 0x01000000u) ? (float)(int)sb : __uint_as_float(sb);
    float inv_sigma = 1.0f / sigma;

    // ---- xT build: x[c][n0+i-4] -> fp16 at xT[i][c], 136 rows ----
    const float* xb = x + (size_t)bt * Cdim * Ndim;
    #pragma unroll
    for (int it = 0; it < 17; it++) {
        int idx = it * THREADS + tid;
        if (idx < 16 * 136) {
            int cp2 = idx / 136;                 // c pair 0..15
            int i   = idx - cp2 * 136;
            int m   = n0 + i - 4;
            float v0 = 0.0f, v1 = 0.0f;
            if (m >= 0 && m < Ndim) {
                v0 = xb[(size_t)(cp2 * 2) * Ndim + m];
                v1 = xb[(size_t)(cp2 * 2 + 1) * Ndim + m];
            }
            __half2 h2v = __floats2half2_rn(v0, v1);
            *(unsigned*)(sm + OFF_XT + i * PROW + 4 * cp2) = *(unsigned*)&h2v;
        }
    }

    // ---- distance weights ws[k][n] (fp32, applied post-MMA) ----
    const float* cb = coords + (size_t)bt * 3 * Ndim;
    for (int idx = tid; idx < Kdim * TILE_N; idx += THREADS) {
        int k = idx >> 7, n = idx & 127;
        int mc = n0 + n, mt2 = mc + k - 4;
        float cx = 0.f, cy = 0.f, cz = 0.f;
        if (mt2 >= 0 && mt2 < Ndim) { cx = cb[mt2]; cy = cb[Ndim + mt2]; cz = cb[2 * Ndim + mt2]; }
        float dx = cx - cb[mc], dy = cy - cb[Ndim + mc], dz = cz - cb[2 * Ndim + mc];
        float d2 = dx * dx + dy * dy + dz * dz;
        ws[k * 128 + n] = fmaxf(1.0f - sqrtf(d2) * inv_sigma, 0.0f);
    }
    __syncthreads();

    // ---- 9 GEMMs (K=32 each); warp tile 32f x 64n; A direct from gmem ----
    const int fh = warp >> 1;                    // f-half (32 rows)
    const int nh = warp & 1;                     // n-half (64 cols)

    // block index = 72t + 8k + 4fh + 2m + s  (32-uint4 blocks)
    const uint4* afrag = (const uint4*)g_wAf;
    const int abase0 = 72 * t + 4 * fh;

    // B lane offset within a 16nx16k x4 tile
    const uint32_t boff = (uint32_t)(((lane >> 4) * 8 + (lane & 7) + nh * 64) * PROW
                                     + ((lane >> 3) & 1) * 16);

    float acc[2][8][4];
    #pragma unroll
    for (int m = 0; m < 2; m++)
        #pragma unroll
        for (int j = 0; j < 8; j++)
            #pragma unroll
            for (int q = 0; q < 4; q++) acc[m][j][q] = 0.0f;

    const int wcol0 = nh * 64 + (lane & 3) * 2;

    #pragma unroll
    for (int k = 0; k < 9; k++) {
        // A fragments for this k: one coalesced LDG.128 per (m,s), L2-resident
        uint4 av[2][2];
        #pragma unroll
        for (int m = 0; m < 2; m++)
            #pragma unroll
            for (int s = 0; s < 2; s++)
                av[m][s] = __ldg(&afrag[(size_t)(abase0 + k * 8 + m * 2 + s) * 32 + lane]);

        const uint32_t bk = smb + OFF_XT + (uint32_t)k * PROW + boff;

        #pragma unroll
        for (int h2 = 0; h2 < 4; h2++) {         // 16n per substep
            uint32_t b0v[4], b1v[4];
            LDSM_X4(b0v[0], b0v[1], b0v[2], b0v[3],
                    bk + (uint32_t)(h2 * 16) * PROW);
            LDSM_X4(b1v[0], b1v[1], b1v[2], b1v[3],
                    bk + (uint32_t)(h2 * 16) * PROW + 32);

            float tmp[2][2][4];
            // s = 0: init (d = a*b + 0), 8 independent MMAs
            #pragma unroll
            for (int m = 0; m < 2; m++) {
                MMAF16_Z(tmp[m][0], ((uint32_t*)&av[m][0]), b0v[0], b0v[1]);
                MMAF16_Z(tmp[m][1], ((uint32_t*)&av[m][0]), b0v[2], b0v[3]);
            }
            // s = 1: accumulate
            #pragma unroll
            for (int m = 0; m < 2; m++) {
                MMAF16(tmp[m][0], ((uint32_t*)&av[m][1]), b1v[0], b1v[1]);
                MMAF16(tmp[m][1], ((uint32_t*)&av[m][1]), b1v[2], b1v[3]);
            }
            // scale by w[k][n] (exact fp32) and accumulate
            #pragma unroll
            for (int nf = 0; nf < 2; nf++) {
                float2 wv = *(float2*)(ws + k * 128 + wcol0 + h2 * 16 + nf * 8);
                #pragma unroll
                for (int m = 0; m < 2; m++) {
                    acc[m][h2 * 2 + nf][0] += wv.x * tmp[m][nf][0];
                    acc[m][h2 * 2 + nf][1] += wv.y * tmp[m][nf][1];
                    acc[m][h2 * 2 + nf][2] += wv.x * tmp[m][nf][2];
                    acc[m][h2 * 2 + nf][3] += wv.y * tmp[m][nf][3];
                }
            }
        }
    }

    // ---- epilogue: smem transpose per 16-f-row chunk -> coalesced float4 STG ----
    float* stage = (float*)sm;                   // pitch SPITCH floats, 8448 B used
    float* ob = out + (size_t)bt * Fdim * Ndim;
    const int drow = lane >> 2;
    const int dcol = (lane & 3) * 2;
    #pragma unroll
    for (int chunk = 0; chunk < 4; chunk++) {
        const int cfh = chunk >> 1, cm = chunk & 1;
        __syncthreads();                         // stage free (also retires xT use)
        if (fh == cfh) {
            #pragma unroll
            for (int j = 0; j < 8; j++) {
                int col = nh * 64 + j * 8 + dcol;
                *(float2*)&stage[drow * SPITCH + col] =
                    make_float2(acc[cm][j][0], acc[cm][j][1]);
                *(float2*)&stage[(drow + 8) * SPITCH + col] =
                    make_float2(acc[cm][j][2], acc[cm][j][3]);
            }
        }
        __syncthreads();                         // stage full
        const int f0 = chunk * 16;
        #pragma unroll
        for (int it = 0; it < 4; it++) {
            int idx = it * THREADS + tid;
            int r2  = idx >> 5;
            int c4  = (idx & 31) * 4;
            float4 v = *(float4*)&stage[r2 * SPITCH + c4];
            *(float4*)&ob[(size_t)(f0 + r2) * Ndim + n0 + c4] = v;
        }
    }
}

extern "C" void kernel_launch(void* const* d_in, const int* in_sizes, int n_in,
                              void* d_out, int out_size)
{
    const float*    x      = (const float*)d_in[0];
    const float*    coords = (const float*)d_in[1];
    const float*    w      = (const float*)d_in[2];
    const unsigned* sigma  = (const unsigned*)d_in[3];
    float*          out    = (float*)d_out;

    prep_w<<<(Tdim * Kdim * 2 * 2 * 2 * 128 + 255) / 256, 256>>>(w);

    dim3 grid(Ndim / TILE_N, Bdim * Tdim);
    sepconv_mma_kernel<<<grid, THREADS, SMEM_TOTAL>>>(x, coords, sigma, out);
}